// round 8
// baseline (speedup 1.0000x reference)
#include <cuda_runtime.h>
#include <math_constants.h>

#define BB      8
#define HDIM    4096
#define NHEADS  32
#define HD      128
#define N3      12288          // 3*HDIM
#define KS1     32             // K-splits for qkv gemm
#define KC1     (HDIM / KS1)   // 128
#define KS2     64             // K-splits for proj gemm
#define KC2     (HDIM / KS2)   // 64
#define TSPLIT  8              // T-splits for flash decode

// ---------------- scratch (allocation-free) ----------------
__device__ __align__(16) float g_qkv_part[(size_t)KS1 * BB * N3];    // 12.6 MB
__device__ __align__(16) float g_qkv[BB * N3];
__device__ __align__(16) float g_proj_part[(size_t)KS2 * BB * HDIM]; // 8.4 MB
__device__ __align__(16) float g_ctx[BB * HDIM];
__device__ __align__(16) float g_pm[BB * NHEADS * TSPLIT];
__device__ __align__(16) float g_pl[BB * NHEADS * TSPLIT];
__device__ __align__(16) float g_pacc[BB * NHEADS * TSPLIT * HD];

// packed f32x2 fma (Blackwell): d = a*b + c on two lanes
__device__ __forceinline__ unsigned long long fma_f32x2(unsigned long long a,
                                                        unsigned long long b,
                                                        unsigned long long c) {
    unsigned long long d;
    asm("fma.rn.f32x2 %0, %1, %2, %3;" : "=l"(d) : "l"(a), "l"(b), "l"(c));
    return d;
}

// ---------------- split-K GEMV: part[split][b][col] = sum_k X[b][k]*W[k][col] ----------------
template <int N, int KCHUNK, bool PROJ>
__global__ __launch_bounds__(256) void gemm_partial_kernel(const float* __restrict__ Xin,
                                                           const float* __restrict__ W) {
    __shared__ unsigned long long xs[BB * KCHUNK];  // x value broadcast-packed into both f32 lanes
    const float* X = PROJ ? g_ctx : Xin;
    const int tid = threadIdx.x;
    const int k0  = blockIdx.y * KCHUNK;

    for (int i = tid; i < BB * KCHUNK; i += 256) {
        const int b = i / KCHUNK, kk = i - b * KCHUNK;
        const unsigned int u = __float_as_uint(X[b * HDIM + k0 + kk]);
        xs[i] = ((unsigned long long)u << 32) | u;
    }
    __syncthreads();

    const int col = blockIdx.x * 512 + tid * 2;
    unsigned long long acc[BB];
#pragma unroll
    for (int b = 0; b < BB; ++b) acc[b] = 0ull;  // bit pattern (0.f, 0.f)

    const unsigned long long* wp =
        reinterpret_cast<const unsigned long long*>(W + (size_t)k0 * N + col);
#pragma unroll 4
    for (int kk = 0; kk < KCHUNK; ++kk) {
        const unsigned long long w = *wp;
        wp += N / 2;
#pragma unroll
        for (int b = 0; b < BB; ++b)
            acc[b] = fma_f32x2(w, xs[b * KCHUNK + kk], acc[b]);
    }

    float* part = PROJ ? g_proj_part : g_qkv_part;
    const size_t base = (size_t)blockIdx.y * BB * N + col;
#pragma unroll
    for (int b = 0; b < BB; ++b)
        *reinterpret_cast<unsigned long long*>(part + base + (size_t)b * N) = acc[b];
}

// ---------------- deterministic split-K reduce + bias ----------------
template <int N, int NSPLIT, bool PROJ>
__global__ __launch_bounds__(256) void reduce_bias_kernel(const float* __restrict__ bias,
                                                          float* __restrict__ outp) {
    const int idx = blockIdx.x * 256 + threadIdx.x;
    if (idx >= BB * N) return;
    const int b = idx / N, j = idx - b * N;
    const float* part = PROJ ? g_proj_part : g_qkv_part;
    float s = bias[j];
#pragma unroll
    for (int p = 0; p < NSPLIT; ++p)
        s += part[((size_t)p * BB + b) * N + j];
    float* out = PROJ ? outp : g_qkv;
    out[idx] = s;
}

// ---------------- flash-decode attention partials ----------------
__global__ __launch_bounds__(128) void attn_partial_kernel(const float* __restrict__ ck,
                                                           const float* __restrict__ cv,
                                                           int P, int T, int chunk) {
    const int bh = blockIdx.x;
    const int b = bh >> 5, h = bh & (NHEADS - 1);
    const int split = blockIdx.y;
    const int t0 = split * chunk;
    const int t1 = min(t0 + chunk, T);

    __shared__ __align__(16) float qs[HD];
    __shared__ float wm[4], wl[4];
    __shared__ __align__(16) float wacc[4][HD];

    const int tid = threadIdx.x, wid = tid >> 5, lane = tid & 31;
    if (tid < HD) qs[tid] = g_qkv[b * N3 + h * HD + tid];
    __syncthreads();

    const float4 q4 = *reinterpret_cast<const float4*>(qs + lane * 4);
    const float scale = 0.08838834764831845f;  // 1/sqrt(128)

    float m = -CUDART_INF_F, l = 0.f;
    float ax = 0.f, ay = 0.f, az = 0.f, aw = 0.f;

    const size_t tstride = (size_t)BB * NHEADS * HD;
    const size_t bhoff = ((size_t)b * NHEADS + h) * HD + lane * 4;
    const float* knew = g_qkv + b * N3 + HDIM     + h * HD + lane * 4;
    const float* vnew = g_qkv + b * N3 + 2 * HDIM + h * HD + lane * 4;

#pragma unroll 2
    for (int t = t0 + wid; t < t1; t += 4) {
        const float *kp, *vp;
        if (t < P) {
            const size_t o = (size_t)t * tstride + bhoff;
            kp = ck + o; vp = cv + o;
        } else {
            kp = knew; vp = vnew;
        }
        const float4 k4 = *reinterpret_cast<const float4*>(kp);
        const float4 v4 = *reinterpret_cast<const float4*>(vp);

        float s = k4.x * q4.x;
        s = fmaf(k4.y, q4.y, s);
        s = fmaf(k4.z, q4.z, s);
        s = fmaf(k4.w, q4.w, s);
        s += __shfl_xor_sync(0xffffffffu, s, 16);
        s += __shfl_xor_sync(0xffffffffu, s, 8);
        s += __shfl_xor_sync(0xffffffffu, s, 4);
        s += __shfl_xor_sync(0xffffffffu, s, 2);
        s += __shfl_xor_sync(0xffffffffu, s, 1);
        s *= scale;

        const float nm   = fmaxf(m, s);
        const float corr = __expf(m - nm);   // first iter: exp(-inf)=0
        const float p    = __expf(s - nm);
        l  = fmaf(l,  corr, p);
        ax = fmaf(ax, corr, p * v4.x);
        ay = fmaf(ay, corr, p * v4.y);
        az = fmaf(az, corr, p * v4.z);
        aw = fmaf(aw, corr, p * v4.w);
        m = nm;
    }

    if (lane == 0) { wm[wid] = m; wl[wid] = l; }
    *reinterpret_cast<float4*>(&wacc[wid][lane * 4]) = make_float4(ax, ay, az, aw);
    __syncthreads();

    if (tid < HD) {
        const float M = fmaxf(fmaxf(wm[0], wm[1]), fmaxf(wm[2], wm[3]));
        float L = 0.f, A = 0.f;
#pragma unroll
        for (int w = 0; w < 4; ++w) {
            const float f = (wm[w] == -CUDART_INF_F) ? 0.f : __expf(wm[w] - M);
            L = fmaf(f, wl[w], L);
            A = fmaf(f, wacc[w][tid], A);
        }
        const int pi = bh * TSPLIT + split;
        g_pacc[pi * HD + tid] = A;
        if (tid == 0) { g_pm[pi] = M; g_pl[pi] = L; }
    }
}

// ---------------- combine T-splits -> context ----------------
__global__ __launch_bounds__(HD) void attn_combine_kernel() {
    const int bh = blockIdx.x;
    const int d  = threadIdx.x;
    float M = -CUDART_INF_F;
#pragma unroll
    for (int s = 0; s < TSPLIT; ++s) M = fmaxf(M, g_pm[bh * TSPLIT + s]);
    float L = 0.f, A = 0.f;
#pragma unroll
    for (int s = 0; s < TSPLIT; ++s) {
        const float mm = g_pm[bh * TSPLIT + s];
        const float f = (mm == -CUDART_INF_F) ? 0.f : __expf(mm - M);
        L = fmaf(f, g_pl[bh * TSPLIT + s], L);
        A = fmaf(f, g_pacc[(bh * TSPLIT + s) * HD + d], A);
    }
    const int b = bh >> 5, h = bh & (NHEADS - 1);
    g_ctx[b * HDIM + h * HD + d] = A / L;
}

// ---------------- launcher ----------------
extern "C" void kernel_launch(void* const* d_in, const int* in_sizes, int n_in,
                              void* d_out, int out_size) {
    const float* x     = (const float*)d_in[0];
    const float* ck    = (const float*)d_in[1];
    const float* cv    = (const float*)d_in[2];
    const float* Wqkv  = (const float*)d_in[3];
    const float* bqkv  = (const float*)d_in[4];
    const float* Wproj = (const float*)d_in[5];
    const float* bproj = (const float*)d_in[6];

    const int P = in_sizes[1] / (BB * NHEADS * HD);   // 2047
    const int T = P + 1;
    const int chunk = (T + TSPLIT - 1) / TSPLIT;

    // 1) qkv = x @ Wqkv (+ bqkv in reduce)
    gemm_partial_kernel<N3, KC1, false><<<dim3(N3 / 512, KS1), 256>>>(x, Wqkv);
    reduce_bias_kernel<N3, KS1, false><<<(BB * N3 + 255) / 256, 256>>>(bqkv, nullptr);

    // 2) flash-decode attention over cache + new token (no cache copy)
    attn_partial_kernel<<<dim3(BB * NHEADS, TSPLIT), 128>>>(ck, cv, P, T, chunk);
    attn_combine_kernel<<<BB * NHEADS, HD>>>();

    // 3) out = ctx @ Wproj + bproj
    gemm_partial_kernel<HDIM, KC2, true><<<dim3(HDIM / 512, KS2), 256>>>(nullptr, Wproj);
    reduce_bias_kernel<HDIM, KS2, true><<<(BB * HDIM + 255) / 256, 256>>>(bproj, (float*)d_out);
}

// round 9
// speedup vs baseline: 1.0146x; 1.0146x over previous
#include <cuda_runtime.h>
#include <math_constants.h>

#define BB      8
#define HDIM    4096
#define NHEADS  32
#define HD      128
#define N3      12288          // 3*HDIM
#define KS1     32             // K-splits for qkv gemm
#define KC1     (HDIM / KS1)   // 128
#define KS2     64             // K-splits for proj gemm
#define KC2     (HDIM / KS2)   // 64
#define TSPLIT  8              // T-splits for flash decode
#define CHUNK_MAX 256          // ceil(2048 / TSPLIT)

// ---------------- scratch (allocation-free) ----------------
__device__ __align__(16) float g_qkv_part[(size_t)KS1 * BB * N3];    // 12.6 MB
__device__ __align__(16) float g_qkv[BB * N3];
__device__ __align__(16) float g_proj_part[(size_t)KS2 * BB * HDIM]; // 8.4 MB
__device__ __align__(16) float g_pm[BB * NHEADS * TSPLIT];
__device__ __align__(16) float g_pl[BB * NHEADS * TSPLIT];
__device__ __align__(16) float g_pacc[BB * NHEADS * TSPLIT * HD];

// packed f32x2 fma (Blackwell): d = a*b + c on two lanes
__device__ __forceinline__ unsigned long long fma_f32x2(unsigned long long a,
                                                        unsigned long long b,
                                                        unsigned long long c) {
    unsigned long long d;
    asm("fma.rn.f32x2 %0, %1, %2, %3;" : "=l"(d) : "l"(a), "l"(b), "l"(c));
    return d;
}

__device__ __forceinline__ unsigned long long pack2(float v) {
    const unsigned int u = __float_as_uint(v);
    return ((unsigned long long)u << 32) | u;
}

// ---------------- split-K GEMV (qkv): part[split][b][col] = sum_k X[b][k]*W[k][col] ----------------
__global__ __launch_bounds__(256) void qkv_gemm_partial_kernel(const float* __restrict__ X,
                                                               const float* __restrict__ W) {
    __shared__ unsigned long long xs[BB * KC1];
    const int tid = threadIdx.x;
    const int k0  = blockIdx.y * KC1;

    for (int i = tid; i < BB * KC1; i += 256) {
        const int b = i / KC1, kk = i - b * KC1;
        xs[i] = pack2(X[b * HDIM + k0 + kk]);
    }
    __syncthreads();

    const int col = blockIdx.x * 512 + tid * 2;
    unsigned long long acc[BB];
#pragma unroll
    for (int b = 0; b < BB; ++b) acc[b] = 0ull;

    const unsigned long long* wp =
        reinterpret_cast<const unsigned long long*>(W + (size_t)k0 * N3 + col);
#pragma unroll 4
    for (int kk = 0; kk < KC1; ++kk) {
        const unsigned long long w = *wp;
        wp += N3 / 2;
#pragma unroll
        for (int b = 0; b < BB; ++b)
            acc[b] = fma_f32x2(w, xs[b * KC1 + kk], acc[b]);
    }

    const size_t base = (size_t)blockIdx.y * BB * N3 + col;
#pragma unroll
    for (int b = 0; b < BB; ++b)
        *reinterpret_cast<unsigned long long*>(g_qkv_part + base + (size_t)b * N3) = acc[b];
}

// ---------------- deterministic split-K reduce + bias ----------------
template <int N, int NSPLIT, bool PROJ>
__global__ __launch_bounds__(256) void reduce_bias_kernel(const float* __restrict__ bias,
                                                          float* __restrict__ outp) {
    const int idx = blockIdx.x * 256 + threadIdx.x;
    if (idx >= BB * N) return;
    const int b = idx / N, j = idx - b * N;
    const float* part = PROJ ? g_proj_part : g_qkv_part;
    float s = bias[j];
#pragma unroll
    for (int p = 0; p < NSPLIT; ++p)
        s += part[((size_t)p * BB + b) * N + j];
    float* out = PROJ ? outp : g_qkv;
    out[idx] = s;
}

// ---------------- flash-decode attention partials (two-pass per chunk) ----------------
__global__ __launch_bounds__(128) void attn_partial_kernel(const float* __restrict__ ck,
                                                           const float* __restrict__ cv,
                                                           int P, int T, int chunk) {
    const int bh = blockIdx.x;
    const int b = bh >> 5, h = bh & (NHEADS - 1);
    const int split = blockIdx.y;
    const int t0 = split * chunk;
    const int t1 = min(t0 + chunk, T);

    __shared__ __align__(16) float qs[HD];
    __shared__ float ss[CHUNK_MAX];
    __shared__ float wm[4], wl[4];
    __shared__ __align__(16) float wacc[4][HD];

    const int tid = threadIdx.x, wid = tid >> 5, lane = tid & 31;
    if (tid < HD) qs[tid] = g_qkv[b * N3 + h * HD + tid];
    __syncthreads();

    const float4 q4 = *reinterpret_cast<const float4*>(qs + lane * 4);
    const float scale = 0.08838834764831845f;  // 1/sqrt(128)

    const size_t tstride = (size_t)BB * NHEADS * HD;
    const size_t bhoff = ((size_t)b * NHEADS + h) * HD + lane * 4;
    const float* knew = g_qkv + b * N3 + HDIM     + h * HD + lane * 4;
    const float* vnew = g_qkv + b * N3 + 2 * HDIM + h * HD + lane * 4;

    // ---- pass A: scores (independent iterations -> high MLP) ----
    float mloc = -CUDART_INF_F;
#pragma unroll 4
    for (int t = t0 + wid; t < t1; t += 4) {
        const float* kp = (t < P) ? (ck + (size_t)t * tstride + bhoff) : knew;
        const float4 k4 = *reinterpret_cast<const float4*>(kp);
        float s = k4.x * q4.x;
        s = fmaf(k4.y, q4.y, s);
        s = fmaf(k4.z, q4.z, s);
        s = fmaf(k4.w, q4.w, s);
        s += __shfl_xor_sync(0xffffffffu, s, 16);
        s += __shfl_xor_sync(0xffffffffu, s, 8);
        s += __shfl_xor_sync(0xffffffffu, s, 4);
        s += __shfl_xor_sync(0xffffffffu, s, 2);
        s += __shfl_xor_sync(0xffffffffu, s, 1);
        s *= scale;
        mloc = fmaxf(mloc, s);
        if (lane == 0) ss[t - t0] = s;
    }
    if (lane == 0) wm[wid] = mloc;
    __syncthreads();

    const float M = fmaxf(fmaxf(wm[0], wm[1]), fmaxf(wm[2], wm[3]));

    // ---- pass B: weighted V accumulation (only a 4-cyc fma chain) ----
    float l = 0.f, ax = 0.f, ay = 0.f, az = 0.f, aw = 0.f;
#pragma unroll 4
    for (int t = t0 + wid; t < t1; t += 4) {
        const float* vp = (t < P) ? (cv + (size_t)t * tstride + bhoff) : vnew;
        const float4 v4 = *reinterpret_cast<const float4*>(vp);
        const float p = __expf(ss[t - t0] - M);
        l += p;
        ax = fmaf(p, v4.x, ax);
        ay = fmaf(p, v4.y, ay);
        az = fmaf(p, v4.z, az);
        aw = fmaf(p, v4.w, aw);
    }

    if (lane == 0) wl[wid] = l;
    *reinterpret_cast<float4*>(&wacc[wid][lane * 4]) = make_float4(ax, ay, az, aw);
    __syncthreads();

    if (tid < HD) {
        const float L = (wl[0] + wl[1]) + (wl[2] + wl[3]);
        const float A = (wacc[0][tid] + wacc[1][tid]) + (wacc[2][tid] + wacc[3][tid]);
        const int pi = bh * TSPLIT + split;
        g_pacc[pi * HD + tid] = A;
        if (tid == 0) { g_pm[pi] = M; g_pl[pi] = L; }
    }
}

// ---------------- proj GEMM with fused split-combine (ctx built in smem phase) ----------------
__global__ __launch_bounds__(256) void proj_gemm_fused_kernel(const float* __restrict__ W) {
    __shared__ unsigned long long xs[BB * KC2];
    const int tid = threadIdx.x;
    const int k0  = blockIdx.y * KC2;

    // reconstruct ctx[b][k0+kk] from attention split-partials
    for (int i = tid; i < BB * KC2; i += 256) {
        const int b = i / KC2, kk = i - b * KC2;
        const int j = k0 + kk;            // 0..4095
        const int h = j >> 7, d = j & (HD - 1);
        const int base = (b * NHEADS + h) * TSPLIT;

        float M = -CUDART_INF_F;
#pragma unroll
        for (int s = 0; s < TSPLIT; ++s) M = fmaxf(M, g_pm[base + s]);
        float L = 0.f, A = 0.f;
#pragma unroll
        for (int s = 0; s < TSPLIT; ++s) {
            const float f = __expf(g_pm[base + s] - M);
            L = fmaf(f, g_pl[base + s], L);
            A = fmaf(f, g_pacc[(base + s) * HD + d], A);
        }
        xs[i] = pack2(A / L);
    }
    __syncthreads();

    const int col = blockIdx.x * 512 + tid * 2;
    unsigned long long acc[BB];
#pragma unroll
    for (int b = 0; b < BB; ++b) acc[b] = 0ull;

    const unsigned long long* wp =
        reinterpret_cast<const unsigned long long*>(W + (size_t)k0 * HDIM + col);
#pragma unroll 4
    for (int kk = 0; kk < KC2; ++kk) {
        const unsigned long long w = *wp;
        wp += HDIM / 2;
#pragma unroll
        for (int b = 0; b < BB; ++b)
            acc[b] = fma_f32x2(w, xs[b * KC2 + kk], acc[b]);
    }

    const size_t base = (size_t)blockIdx.y * BB * HDIM + col;
#pragma unroll
    for (int b = 0; b < BB; ++b)
        *reinterpret_cast<unsigned long long*>(g_proj_part + base + (size_t)b * HDIM) = acc[b];
}

// ---------------- launcher ----------------
extern "C" void kernel_launch(void* const* d_in, const int* in_sizes, int n_in,
                              void* d_out, int out_size) {
    const float* x     = (const float*)d_in[0];
    const float* ck    = (const float*)d_in[1];
    const float* cv    = (const float*)d_in[2];
    const float* Wqkv  = (const float*)d_in[3];
    const float* bqkv  = (const float*)d_in[4];
    const float* Wproj = (const float*)d_in[5];
    const float* bproj = (const float*)d_in[6];

    const int P = in_sizes[1] / (BB * NHEADS * HD);   // 2047
    const int T = P + 1;
    const int chunk = (T + TSPLIT - 1) / TSPLIT;      // 256

    // 1) qkv = x @ Wqkv (+ bqkv in reduce)
    qkv_gemm_partial_kernel<<<dim3(N3 / 512, KS1), 256>>>(x, Wqkv);
    reduce_bias_kernel<N3, KS1, false><<<(BB * N3 + 255) / 256, 256>>>(bqkv, nullptr);

    // 2) flash-decode attention over cache + new token (no cache copy)
    attn_partial_kernel<<<dim3(BB * NHEADS, TSPLIT), 128>>>(ck, cv, P, T, chunk);

    // 3) out = ctx @ Wproj + bproj  (ctx combined inside the gemm's smem phase)
    proj_gemm_fused_kernel<<<dim3(HDIM / 512, KS2), 256>>>(Wproj);
    reduce_bias_kernel<HDIM, KS2, true><<<(BB * HDIM + 255) / 256, 256>>>(bproj, (float*)d_out);
}

// round 10
// speedup vs baseline: 1.0352x; 1.0203x over previous
#include <cuda_runtime.h>
#include <math_constants.h>

#define BB      8
#define HDIM    4096
#define NHEADS  32
#define HD      128
#define N3      12288          // 3*HDIM
#define KS1     64             // K-splits for qkv gemm
#define KC1     (HDIM / KS1)   // 64
#define KS2     128            // K-splits for proj gemm
#define KC2     (HDIM / KS2)   // 32
#define TSPLIT  8              // T-splits for flash decode
#define CHUNK_MAX 256          // ceil(2048 / TSPLIT)
#define PF      8              // load-pipeline depth in GEMVs

// ---------------- scratch (allocation-free) ----------------
__device__ __align__(16) float g_qkv_part[(size_t)KS1 * BB * N3];    // 25.2 MB
__device__ __align__(16) float g_qkv[BB * N3];
__device__ __align__(16) float g_proj_part[(size_t)KS2 * BB * HDIM]; // 16.8 MB
__device__ __align__(16) float g_pm[BB * NHEADS * TSPLIT];
__device__ __align__(16) float g_pl[BB * NHEADS * TSPLIT];
__device__ __align__(16) float g_pacc[BB * NHEADS * TSPLIT * HD];

// packed f32x2 fma (Blackwell): d = a*b + c on two lanes
__device__ __forceinline__ unsigned long long fma_f32x2(unsigned long long a,
                                                        unsigned long long b,
                                                        unsigned long long c) {
    unsigned long long d;
    asm("fma.rn.f32x2 %0, %1, %2, %3;" : "=l"(d) : "l"(a), "l"(b), "l"(c));
    return d;
}

__device__ __forceinline__ unsigned long long pack2(float v) {
    const unsigned int u = __float_as_uint(v);
    return ((unsigned long long)u << 32) | u;
}

// ---------------- split-K GEMV core: 8-deep load pipeline ----------------
template <int N, int KCHUNK>
__device__ __forceinline__ void gemv_core(const unsigned long long* __restrict__ xs,
                                          const float* __restrict__ W,
                                          float* __restrict__ part,
                                          int k0, int col, int splitIdx) {
    unsigned long long acc[BB];
#pragma unroll
    for (int b = 0; b < BB; ++b) acc[b] = 0ull;

    const unsigned long long* wp =
        reinterpret_cast<const unsigned long long*>(W + (size_t)k0 * N + col);

#pragma unroll
    for (int kk0 = 0; kk0 < KCHUNK; kk0 += PF) {
        unsigned long long w[PF];
#pragma unroll
        for (int u = 0; u < PF; ++u)               // front-batched: MLP = PF
            w[u] = wp[(size_t)(kk0 + u) * (N / 2)];
#pragma unroll
        for (int u = 0; u < PF; ++u)
#pragma unroll
            for (int b = 0; b < BB; ++b)
                acc[b] = fma_f32x2(w[u], xs[b * KCHUNK + kk0 + u], acc[b]);
    }

    const size_t base = (size_t)splitIdx * BB * N + col;
#pragma unroll
    for (int b = 0; b < BB; ++b)
        *reinterpret_cast<unsigned long long*>(part + base + (size_t)b * N) = acc[b];
}

// ---------------- qkv GEMV ----------------
__global__ __launch_bounds__(256) void qkv_gemm_partial_kernel(const float* __restrict__ X,
                                                               const float* __restrict__ W) {
    __shared__ unsigned long long xs[BB * KC1];
    const int tid = threadIdx.x;
    const int k0  = blockIdx.y * KC1;

    for (int i = tid; i < BB * KC1; i += 256) {
        const int b = i / KC1, kk = i - b * KC1;
        xs[i] = pack2(X[b * HDIM + k0 + kk]);
    }
    __syncthreads();

    gemv_core<N3, KC1>(xs, W, g_qkv_part, k0, blockIdx.x * 512 + tid * 2, blockIdx.y);
}

// ---------------- deterministic split-K reduce + bias (float2) ----------------
template <int N, int NSPLIT, bool PROJ>
__global__ __launch_bounds__(256) void reduce_bias_kernel(const float* __restrict__ bias,
                                                          float* __restrict__ outp) {
    const int idx2 = blockIdx.x * 256 + threadIdx.x;     // float2 index
    if (idx2 >= BB * N / 2) return;
    const int b = idx2 / (N / 2), j2 = idx2 - b * (N / 2);
    const float* part = PROJ ? g_proj_part : g_qkv_part;
    const float2* bias2 = reinterpret_cast<const float2*>(bias);
    float2 s = bias2[j2];
#pragma unroll
    for (int p = 0; p < NSPLIT; ++p) {
        const float2 v = *reinterpret_cast<const float2*>(
            part + ((size_t)p * BB + b) * N + 2 * j2);
        s.x += v.x; s.y += v.y;
    }
    float* out = PROJ ? outp : g_qkv;
    *reinterpret_cast<float2*>(out + b * N + 2 * j2) = s;
}

// ---------------- flash-decode attention partials (two-pass per chunk) ----------------
__global__ __launch_bounds__(128) void attn_partial_kernel(const float* __restrict__ ck,
                                                           const float* __restrict__ cv,
                                                           int P, int T, int chunk) {
    const int bh = blockIdx.x;
    const int b = bh >> 5, h = bh & (NHEADS - 1);
    const int split = blockIdx.y;
    const int t0 = split * chunk;
    const int t1 = min(t0 + chunk, T);

    __shared__ __align__(16) float qs[HD];
    __shared__ float ss[CHUNK_MAX];
    __shared__ float wm[4], wl[4];
    __shared__ __align__(16) float wacc[4][HD];

    const int tid = threadIdx.x, wid = tid >> 5, lane = tid & 31;
    if (tid < HD) qs[tid] = g_qkv[b * N3 + h * HD + tid];
    __syncthreads();

    const float4 q4 = *reinterpret_cast<const float4*>(qs + lane * 4);
    const float scale = 0.08838834764831845f;  // 1/sqrt(128)

    const size_t tstride = (size_t)BB * NHEADS * HD;
    const size_t bhoff = ((size_t)b * NHEADS + h) * HD + lane * 4;
    const float* knew = g_qkv + b * N3 + HDIM     + h * HD + lane * 4;
    const float* vnew = g_qkv + b * N3 + 2 * HDIM + h * HD + lane * 4;

    // ---- pass A: scores (independent iterations -> high MLP) ----
    float mloc = -CUDART_INF_F;
#pragma unroll 8
    for (int t = t0 + wid; t < t1; t += 4) {
        const float* kp = (t < P) ? (ck + (size_t)t * tstride + bhoff) : knew;
        const float4 k4 = *reinterpret_cast<const float4*>(kp);
        float s = k4.x * q4.x;
        s = fmaf(k4.y, q4.y, s);
        s = fmaf(k4.z, q4.z, s);
        s = fmaf(k4.w, q4.w, s);
        s += __shfl_xor_sync(0xffffffffu, s, 16);
        s += __shfl_xor_sync(0xffffffffu, s, 8);
        s += __shfl_xor_sync(0xffffffffu, s, 4);
        s += __shfl_xor_sync(0xffffffffu, s, 2);
        s += __shfl_xor_sync(0xffffffffu, s, 1);
        s *= scale;
        mloc = fmaxf(mloc, s);
        if (lane == 0) ss[t - t0] = s;
    }
    if (lane == 0) wm[wid] = mloc;
    __syncthreads();

    const float M = fmaxf(fmaxf(wm[0], wm[1]), fmaxf(wm[2], wm[3]));

    // ---- pass B: weighted V accumulation (only a 4-cyc fma chain) ----
    float l = 0.f, ax = 0.f, ay = 0.f, az = 0.f, aw = 0.f;
#pragma unroll 8
    for (int t = t0 + wid; t < t1; t += 4) {
        const float* vp = (t < P) ? (cv + (size_t)t * tstride + bhoff) : vnew;
        const float4 v4 = *reinterpret_cast<const float4*>(vp);
        const float p = __expf(ss[t - t0] - M);
        l += p;
        ax = fmaf(p, v4.x, ax);
        ay = fmaf(p, v4.y, ay);
        az = fmaf(p, v4.z, az);
        aw = fmaf(p, v4.w, aw);
    }

    if (lane == 0) wl[wid] = l;
    *reinterpret_cast<float4*>(&wacc[wid][lane * 4]) = make_float4(ax, ay, az, aw);
    __syncthreads();

    if (tid < HD) {
        const float L = (wl[0] + wl[1]) + (wl[2] + wl[3]);
        const float A = (wacc[0][tid] + wacc[1][tid]) + (wacc[2][tid] + wacc[3][tid]);
        const int pi = bh * TSPLIT + split;
        g_pacc[pi * HD + tid] = A;
        if (tid == 0) { g_pm[pi] = M; g_pl[pi] = L; }
    }
}

// ---------------- proj GEMM with fused split-combine (ctx built in smem phase) ----------------
__global__ __launch_bounds__(256) void proj_gemm_fused_kernel(const float* __restrict__ W) {
    __shared__ unsigned long long xs[BB * KC2];
    const int tid = threadIdx.x;
    const int k0  = blockIdx.y * KC2;

    // reconstruct ctx[b][k0+kk] from attention split-partials
    for (int i = tid; i < BB * KC2; i += 256) {
        const int b = i / KC2, kk = i - b * KC2;
        const int j = k0 + kk;            // 0..4095
        const int h = j >> 7, d = j & (HD - 1);
        const int base = (b * NHEADS + h) * TSPLIT;

        float M = -CUDART_INF_F;
#pragma unroll
        for (int s = 0; s < TSPLIT; ++s) M = fmaxf(M, g_pm[base + s]);
        float L = 0.f, A = 0.f;
#pragma unroll
        for (int s = 0; s < TSPLIT; ++s) {
            const float f = __expf(g_pm[base + s] - M);
            L = fmaf(f, g_pl[base + s], L);
            A = fmaf(f, g_pacc[(base + s) * HD + d], A);
        }
        xs[i] = pack2(A / L);
    }
    __syncthreads();

    gemv_core<HDIM, KC2>(xs, W, g_proj_part, k0, blockIdx.x * 512 + tid * 2, blockIdx.y);
}

// ---------------- launcher ----------------
extern "C" void kernel_launch(void* const* d_in, const int* in_sizes, int n_in,
                              void* d_out, int out_size) {
    const float* x     = (const float*)d_in[0];
    const float* ck    = (const float*)d_in[1];
    const float* cv    = (const float*)d_in[2];
    const float* Wqkv  = (const float*)d_in[3];
    const float* bqkv  = (const float*)d_in[4];
    const float* Wproj = (const float*)d_in[5];
    const float* bproj = (const float*)d_in[6];

    const int P = in_sizes[1] / (BB * NHEADS * HD);   // 2047
    const int T = P + 1;
    const int chunk = (T + TSPLIT - 1) / TSPLIT;      // 256

    // 1) qkv = x @ Wqkv (+ bqkv in reduce)
    qkv_gemm_partial_kernel<<<dim3(N3 / 512, KS1), 256>>>(x, Wqkv);
    reduce_bias_kernel<N3, KS1, false><<<(BB * N3 / 2 + 255) / 256, 256>>>(bqkv, nullptr);

    // 2) flash-decode attention over cache + new token (no cache copy)
    attn_partial_kernel<<<dim3(BB * NHEADS, TSPLIT), 128>>>(ck, cv, P, T, chunk);

    // 3) out = ctx @ Wproj + bproj  (ctx combined inside the gemm's smem phase)
    proj_gemm_fused_kernel<<<dim3(HDIM / 512, KS2), 256>>>(Wproj);
    reduce_bias_kernel<HDIM, KS2, true><<<(BB * HDIM / 2 + 255) / 256, 256>>>(bproj, (float*)d_out);
}